// round 1
// baseline (speedup 1.0000x reference)
#include <cuda_runtime.h>

#define NN 100000
#define NE 1600000
#define D 32
#define CUT_K 320000        // int(E * 0.2)
#define EQ_CAP 2048

// ---------------- device scratch (no allocations allowed) ----------------
__device__ float g_nh[NN * D];     // row-normalized h
__device__ float g_hs[NN * D];     // h * norm  (message payload)
__device__ float g_hnew[NN * D];   // aggregation target
__device__ float g_cos[NE];
__device__ float g_norm[NN];
__device__ int   g_deg[NN];
__device__ unsigned char g_eqflag[NE];
__device__ int   g_eq_list[EQ_CAP];
__device__ int   g_eq_count;
__device__ unsigned int g_hist[256];   // stays zero between rounds (resolve clears)
__device__ unsigned int g_prefix;
__device__ int   g_kremain;

// float -> order-preserving uint (ascending)
__device__ __forceinline__ unsigned f2o(float f) {
    unsigned u = __float_as_uint(f);
    return (u & 0x80000000u) ? ~u : (u | 0x80000000u);
}

// ---------------- degree / norm (once per launch) ----------------
__global__ void k_deg_zero() {
    int i = blockIdx.x * blockDim.x + threadIdx.x;
    if (i < NN) g_deg[i] = 0;
}
__global__ void k_deg(const int* __restrict__ dst) {
    int i = blockIdx.x * blockDim.x + threadIdx.x;
    if (i < NE) atomicAdd(&g_deg[dst[i]], 1);
}
__global__ void k_norm() {
    int i = blockIdx.x * blockDim.x + threadIdx.x;
    if (i < NN) {
        float d = (float)g_deg[i];
        if (d < 1.0f) d = 1.0f;
        g_norm[i] = 1.0f / sqrtf(d);
    }
}

// ---------------- per-hop prep: h = hin [*norm];  nh = h/max(||h||,eps);  hs = h*norm
__global__ void k_prep(const float* __restrict__ feat, int hop) {
    int g = blockIdx.x * blockDim.x + threadIdx.x;
    int row = g >> 5, lane = g & 31;
    if (row >= NN) return;
    const float* hin = hop ? g_hnew : feat;
    float nm = g_norm[row];
    float v = hin[row * D + lane];
    if (hop) v *= nm;                 // trailing h*norm from previous hop
    float ss = v * v;
    #pragma unroll
    for (int o = 16; o > 0; o >>= 1) ss += __shfl_xor_sync(0xFFFFFFFFu, ss, o);
    float nrm = sqrtf(ss);
    float inv = 1.0f / fmaxf(nrm, 1e-12f);
    g_nh[row * D + lane] = v * inv;
    g_hs[row * D + lane] = v * nm;    // leading h*norm for messages
}

// ---------------- per-hop init: zero h_new, clear eq flags/scalars ----------------
__global__ void k_hopinit() {
    int i = blockIdx.x * blockDim.x + threadIdx.x;
    if (i < NN * D) g_hnew[i] = 0.0f;
    if (i < NE) g_eqflag[i] = 0;
    if (i == 0) { g_eq_count = 0; g_prefix = 0u; g_kremain = CUT_K; }
}

// ---------------- cosine per edge (warp per edge, 1 L2 line per row) ----------------
__global__ void k_cos(const int* __restrict__ src, const int* __restrict__ dst) {
    int g = blockIdx.x * blockDim.x + threadIdx.x;
    int e = g >> 5, lane = g & 31;
    if (e >= NE) return;
    int s = src[e], d = dst[e];
    float p = g_nh[s * D + lane] * g_nh[d * D + lane];
    #pragma unroll
    for (int o = 16; o > 0; o >>= 1) p += __shfl_xor_sync(0xFFFFFFFFu, p, o);
    if (lane == 0) g_cos[e] = p;
}

// ---------------- radix select: histogram round ----------------
__global__ void k_hist(int shift, unsigned mask) {
    __shared__ unsigned sh[256];
    for (int i = threadIdx.x; i < 256; i += blockDim.x) sh[i] = 0u;
    __syncthreads();
    unsigned pref = g_prefix;
    int stride = gridDim.x * blockDim.x;
    for (int e = blockIdx.x * blockDim.x + threadIdx.x; e < NE; e += stride) {
        unsigned key = f2o(g_cos[e]);
        if ((key & mask) == (pref & mask))
            atomicAdd(&sh[(key >> shift) & 255u], 1u);
    }
    __syncthreads();
    for (int i = threadIdx.x; i < 256; i += blockDim.x)
        if (sh[i]) atomicAdd(&g_hist[i], sh[i]);
}

// ---------------- radix select: resolve round (1 block) ----------------
__global__ void k_resolve(int shift) {
    __shared__ unsigned sh[256];
    int t = threadIdx.x;
    sh[t] = g_hist[t];
    __syncthreads();
    if (t == 0) {
        unsigned cum = 0;
        int kr = g_kremain;
        for (int b = 0; b < 256; b++) {
            unsigned c = sh[b];
            if (cum + c >= (unsigned)kr) {
                g_prefix |= ((unsigned)b) << shift;
                g_kremain = kr - (int)cum;
                break;
            }
            cum += c;
        }
    }
    g_hist[t] = 0u;   // restore invariant for next round / next hop
}

// ---------------- exact tie handling (match top_k lowest-index-first) ----------------
__global__ void k_eq_gather() {
    int e = blockIdx.x * blockDim.x + threadIdx.x;
    if (e >= NE) return;
    if (f2o(g_cos[e]) == g_prefix) {
        int pos = atomicAdd(&g_eq_count, 1);
        if (pos < EQ_CAP) g_eq_list[pos] = e;
    }
}
__global__ void k_eq_mark() {
    int n = g_eq_count; if (n > EQ_CAP) n = EQ_CAP;
    int r = g_kremain;                 // how many of the equal-key edges to drop
    for (int i = threadIdx.x; i < n; i += blockDim.x) {
        int ei = g_eq_list[i];
        int rank = 0;
        for (int j = 0; j < n; j++) rank += (g_eq_list[j] < ei);
        if (rank < r) g_eqflag[ei] = 1;   // drop the r lowest-index ties
    }
}

// ---------------- message scatter (warp per edge, RED f32) ----------------
__global__ void k_scatter(const int* __restrict__ src, const int* __restrict__ dst) {
    int g = blockIdx.x * blockDim.x + threadIdx.x;
    int e = g >> 5, lane = g & 31;
    if (e >= NE) return;
    unsigned key = f2o(g_cos[e]);
    unsigned thr = g_prefix;
    bool keep;
    if (key > thr)      keep = true;
    else if (key < thr) keep = false;
    else                keep = (g_eqflag[e] == 0);
    if (!keep) return;
    int s = src[e], d = dst[e];
    float v = g_hs[s * D + lane];
    atomicAdd(&g_hnew[d * D + lane], v);
}

// ---------------- final: out = (h_new * norm) @ W^T ----------------
__global__ void k_out(const float* __restrict__ W, float* __restrict__ out) {
    __shared__ float sW[32 * 33];
    for (int i = threadIdx.x; i < 1024; i += blockDim.x) {
        int o = i >> 5, k = i & 31;
        sW[o * 33 + k] = W[i];
    }
    __syncthreads();
    int g = blockIdx.x * blockDim.x + threadIdx.x;
    int row = g >> 5, lane = g & 31;
    if (row >= NN) return;
    float hv = g_hnew[row * D + lane] * g_norm[row];
    float acc = 0.0f;
    #pragma unroll
    for (int k = 0; k < 32; k++) {
        float hk = __shfl_sync(0xFFFFFFFFu, hv, k);
        acc += hk * sW[lane * 33 + k];
    }
    out[row * D + lane] = acc;
}

extern "C" void kernel_launch(void* const* d_in, const int* in_sizes, int n_in,
                              void* d_out, int out_size) {
    const float* feat = (const float*)d_in[0];
    const float* W    = (const float*)d_in[1];
    const int*   src  = (const int*)d_in[2];
    const int*   dst  = (const int*)d_in[3];
    float* out = (float*)d_out;

    const int TB = 256;
    const int grid_node  = (NN + TB - 1) / TB;          // node-scalar kernels
    const int grid_edge  = (NE + TB - 1) / TB;          // edge-scalar kernels
    const int grid_rowW  = (NN * 32 + TB - 1) / TB;     // warp-per-row
    const int grid_edgeW = (NE * 32 + TB - 1) / TB;     // warp-per-edge
    const int grid_init  = (NN * D + TB - 1) / TB;

    k_deg_zero<<<grid_node, TB>>>();
    k_deg<<<grid_edge, TB>>>(dst);
    k_norm<<<grid_node, TB>>>();

    for (int hop = 0; hop < 2; hop++) {
        k_prep<<<grid_rowW, TB>>>(feat, hop);
        k_hopinit<<<grid_init, TB>>>();
        k_cos<<<grid_edgeW, TB>>>(src, dst);

        // 4-round MSB radix select for the CUT_K-th smallest cos
        k_hist<<<2048, TB>>>(24, 0x00000000u); k_resolve<<<1, 256>>>(24);
        k_hist<<<2048, TB>>>(16, 0xFF000000u); k_resolve<<<1, 256>>>(16);
        k_hist<<<2048, TB>>>( 8, 0xFFFF0000u); k_resolve<<<1, 256>>>( 8);
        k_hist<<<2048, TB>>>( 0, 0xFFFFFF00u); k_resolve<<<1, 256>>>( 0);

        k_eq_gather<<<grid_edge, TB>>>();
        k_eq_mark<<<1, 256>>>();

        k_scatter<<<grid_edgeW, TB>>>(src, dst);
    }

    k_out<<<grid_rowW, TB>>>(W, out);
}

// round 2
// speedup vs baseline: 1.9940x; 1.9940x over previous
#include <cuda_runtime.h>

#define NN 100000
#define NE 1600000
#define D 32
#define CUT_K 320000        // int(E * 0.2)
#define EQ_CAP 2048

// ---------------- device scratch (no allocations allowed) ----------------
__device__ __align__(16) float g_nh[NN * D];     // row-normalized h
__device__ __align__(16) float g_hs[NN * D];     // h * norm  (message payload)
__device__ __align__(16) float g_hnew[NN * D];   // aggregation target
__device__ unsigned g_key[NE];                   // order-preserving cos keys
__device__ float g_norm[NN];
__device__ int   g_deg[NN];
__device__ __align__(4) unsigned char g_eqflag[NE];
__device__ int   g_eq_list[EQ_CAP];
__device__ int   g_eq_count;
__device__ unsigned int g_hist[256];   // stays zero between rounds (resolve clears)
__device__ unsigned int g_prefix;
__device__ int   g_kremain;

// float -> order-preserving uint (ascending)
__device__ __forceinline__ unsigned f2o(float f) {
    unsigned u = __float_as_uint(f);
    return (u & 0x80000000u) ? ~u : (u | 0x80000000u);
}

// ---------------- degree / norm (once per launch) ----------------
__global__ void k_deg_zero() {
    int i = blockIdx.x * blockDim.x + threadIdx.x;
    if (i < NN) g_deg[i] = 0;
}
__global__ void k_deg(const int* __restrict__ dst) {
    int i = blockIdx.x * blockDim.x + threadIdx.x;
    if (i < NE) atomicAdd(&g_deg[dst[i]], 1);
}
__global__ void k_norm() {
    int i = blockIdx.x * blockDim.x + threadIdx.x;
    if (i < NN) {
        float d = (float)g_deg[i];
        if (d < 1.0f) d = 1.0f;
        g_norm[i] = 1.0f / sqrtf(d);
    }
}

// -------- per-hop prep: 8 lanes/row, float4. nh = h/max(||h||,eps); hs = h*norm
__global__ void k_prep(const float* __restrict__ feat, int hop) {
    int g = blockIdx.x * blockDim.x + threadIdx.x;
    int row = g >> 3, sub = g & 7;
    if (row >= NN) return;
    float nm = g_norm[row];
    const float4* hin4 = hop ? (const float4*)g_hnew : (const float4*)feat;
    float4 v = hin4[row * 8 + sub];
    if (hop) { v.x *= nm; v.y *= nm; v.z *= nm; v.w *= nm; }  // trailing norm, prev hop
    float ss = v.x * v.x + v.y * v.y + v.z * v.z + v.w * v.w;
    #pragma unroll
    for (int o = 4; o > 0; o >>= 1) ss += __shfl_xor_sync(0xFFFFFFFFu, ss, o);
    float inv = 1.0f / fmaxf(sqrtf(ss), 1e-12f);
    ((float4*)g_nh)[row * 8 + sub] = make_float4(v.x * inv, v.y * inv, v.z * inv, v.w * inv);
    ((float4*)g_hs)[row * 8 + sub] = make_float4(v.x * nm,  v.y * nm,  v.z * nm,  v.w * nm);
}

// ---------------- per-hop init (vectorized): zero h_new, clear eq flags/scalars
__global__ void k_hopinit() {
    int i = blockIdx.x * blockDim.x + threadIdx.x;
    if (i < NN * 8) ((float4*)g_hnew)[i] = make_float4(0.f, 0.f, 0.f, 0.f);
    if (i < NE / 4) ((unsigned*)g_eqflag)[i] = 0u;
    if (i == 0) { g_eq_count = 0; g_prefix = 0u; g_kremain = CUT_K; }
}

// ------ cosine per edge (8 lanes/edge, float4) + fused radix round-1 histogram
__global__ void k_cos(const int* __restrict__ src, const int* __restrict__ dst) {
    __shared__ unsigned sh[256];
    for (int i = threadIdx.x; i < 256; i += blockDim.x) sh[i] = 0u;
    __syncthreads();
    int g = blockIdx.x * blockDim.x + threadIdx.x;
    int e = g >> 3, sub = g & 7;
    float p = 0.0f;
    if (e < NE) {
        int s = src[e], d = dst[e];
        float4 a = ((const float4*)g_nh)[s * 8 + sub];
        float4 b = ((const float4*)g_nh)[d * 8 + sub];
        p = a.x * b.x + a.y * b.y + a.z * b.z + a.w * b.w;
    }
    #pragma unroll
    for (int o = 4; o > 0; o >>= 1) p += __shfl_xor_sync(0xFFFFFFFFu, p, o);
    if (e < NE && sub == 0) {
        unsigned key = f2o(p);
        g_key[e] = key;
        atomicAdd(&sh[key >> 24], 1u);
    }
    __syncthreads();
    for (int i = threadIdx.x; i < 256; i += blockDim.x)
        if (sh[i]) atomicAdd(&g_hist[i], sh[i]);
}

// ---------------- radix select: histogram round (reads precomputed keys)
__global__ void k_hist(int shift, unsigned mask) {
    __shared__ unsigned sh[256];
    for (int i = threadIdx.x; i < 256; i += blockDim.x) sh[i] = 0u;
    __syncthreads();
    unsigned pref = g_prefix;
    int stride = gridDim.x * blockDim.x;
    for (int e = blockIdx.x * blockDim.x + threadIdx.x; e < NE; e += stride) {
        unsigned key = g_key[e];
        if ((key & mask) == (pref & mask))
            atomicAdd(&sh[(key >> shift) & 255u], 1u);
    }
    __syncthreads();
    for (int i = threadIdx.x; i < 256; i += blockDim.x)
        if (sh[i]) atomicAdd(&g_hist[i], sh[i]);
}

// ---------------- radix select: resolve round (1 block) ----------------
__global__ void k_resolve(int shift) {
    __shared__ unsigned sh[256];
    int t = threadIdx.x;
    sh[t] = g_hist[t];
    __syncthreads();
    if (t == 0) {
        unsigned cum = 0;
        int kr = g_kremain;
        for (int b = 0; b < 256; b++) {
            unsigned c = sh[b];
            if (cum + c >= (unsigned)kr) {
                g_prefix |= ((unsigned)b) << shift;
                g_kremain = kr - (int)cum;
                break;
            }
            cum += c;
        }
    }
    g_hist[t] = 0u;   // restore invariant for next round / next hop
}

// ---------------- exact tie handling (match top_k lowest-index-first) ----------------
__global__ void k_eq_gather() {
    int e = blockIdx.x * blockDim.x + threadIdx.x;
    if (e >= NE) return;
    if (g_key[e] == g_prefix) {
        int pos = atomicAdd(&g_eq_count, 1);
        if (pos < EQ_CAP) g_eq_list[pos] = e;
    }
}
__global__ void k_eq_mark() {
    int n = g_eq_count; if (n > EQ_CAP) n = EQ_CAP;
    int r = g_kremain;                 // how many of the equal-key edges to drop
    for (int i = threadIdx.x; i < n; i += blockDim.x) {
        int ei = g_eq_list[i];
        int rank = 0;
        for (int j = 0; j < n; j++) rank += (g_eq_list[j] < ei);
        if (rank < r) g_eqflag[ei] = 1;   // drop the r lowest-index ties
    }
}

// -------- message scatter (8 lanes/edge, float4 gather, red.v4 accumulate)
__global__ void k_scatter(const int* __restrict__ src, const int* __restrict__ dst) {
    int g = blockIdx.x * blockDim.x + threadIdx.x;
    int e = g >> 3, sub = g & 7;
    if (e >= NE) return;
    unsigned key = g_key[e];
    unsigned thr = g_prefix;
    bool keep = (key > thr) || (key == thr && g_eqflag[e] == 0);
    if (!keep) return;
    int s = src[e], d = dst[e];
    float4 v = ((const float4*)g_hs)[s * 8 + sub];
    float* p = &g_hnew[d * D + sub * 4];
    asm volatile("red.global.add.v4.f32 [%0], {%1, %2, %3, %4};"
                 :: "l"(p), "f"(v.x), "f"(v.y), "f"(v.z), "f"(v.w) : "memory");
}

// ---------------- final: out = (h_new * norm) @ W^T ----------------
__global__ void k_out(const float* __restrict__ W, float* __restrict__ out) {
    __shared__ float sW[32 * 33];
    for (int i = threadIdx.x; i < 1024; i += blockDim.x) {
        int o = i >> 5, k = i & 31;
        sW[o * 33 + k] = W[i];
    }
    __syncthreads();
    int g = blockIdx.x * blockDim.x + threadIdx.x;
    int row = g >> 5, lane = g & 31;
    if (row >= NN) return;
    float hv = g_hnew[row * D + lane] * g_norm[row];
    float acc = 0.0f;
    #pragma unroll
    for (int k = 0; k < 32; k++) {
        float hk = __shfl_sync(0xFFFFFFFFu, hv, k);
        acc += hk * sW[lane * 33 + k];
    }
    out[row * D + lane] = acc;
}

extern "C" void kernel_launch(void* const* d_in, const int* in_sizes, int n_in,
                              void* d_out, int out_size) {
    const float* feat = (const float*)d_in[0];
    const float* W    = (const float*)d_in[1];
    const int*   src  = (const int*)d_in[2];
    const int*   dst  = (const int*)d_in[3];
    float* out = (float*)d_out;

    const int TB = 256;
    const int grid_node  = (NN + TB - 1) / TB;          // node-scalar kernels
    const int grid_edge  = (NE + TB - 1) / TB;          // edge-scalar kernels
    const int grid_row8  = (NN * 8 + TB - 1) / TB;      // 8 lanes per row
    const int grid_edge8 = (NE * 8 + TB - 1) / TB;      // 8 lanes per edge
    const int grid_rowW  = (NN * 32 + TB - 1) / TB;     // warp-per-row (k_out)
    const int grid_init  = (NN * 8 + TB - 1) / TB;      // covers max(NN*8, NE/4)

    k_deg_zero<<<grid_node, TB>>>();
    k_deg<<<grid_edge, TB>>>(dst);
    k_norm<<<grid_node, TB>>>();

    for (int hop = 0; hop < 2; hop++) {
        k_prep<<<grid_row8, TB>>>(feat, hop);
        k_hopinit<<<grid_init, TB>>>();
        k_cos<<<grid_edge8, TB>>>(src, dst);   // fused round-1 histogram

        // remaining 3 rounds of MSB radix select for the CUT_K-th smallest cos
        k_resolve<<<1, 256>>>(24);
        k_hist<<<2048, TB>>>(16, 0xFF000000u); k_resolve<<<1, 256>>>(16);
        k_hist<<<2048, TB>>>( 8, 0xFFFF0000u); k_resolve<<<1, 256>>>( 8);
        k_hist<<<2048, TB>>>( 0, 0xFFFFFF00u); k_resolve<<<1, 256>>>( 0);

        k_eq_gather<<<grid_edge, TB>>>();
        k_eq_mark<<<1, 256>>>();

        k_scatter<<<grid_edge8, TB>>>(src, dst);
    }

    k_out<<<grid_rowW, TB>>>(W, out);
}